// round 1
// baseline (speedup 1.0000x reference)
#include <cuda_runtime.h>
#include <cuda_bf16.h>
#include <cstdint>
#include <cstdio>

typedef __nv_bfloat16 bf16;

// ---------------- problem dims ----------------
#define B_SZ   512
#define NSNP   20000
#define NGEN   5000
#define NPRO   3000
#define IN_COLS 28000     // NPRO + NGEN + NSNP
#define H1_N   1024
#define H2_N   256

// padded dims (N padded to mult of 128, K padded to mult of 32)
#define NG_P   5120       // N_GEN padded (layer1 out cols)
#define NP_P   3072       // N_PRO padded
#define K2_P   5024       // layer2 K (5000 -> 5024)
#define K3_P   8192       // bridge K = 5120 + 3072
#define K4_P   3008       // layer4 K (3000 -> 3008)
#define K5_P   6144       // fuse K = 3072 + 3072

// ---------------- device scratch (static, zero-init BSS) ----------------
__device__ bf16 g_snp[(size_t)B_SZ * NSNP];
__device__ bf16 g_gen[(size_t)B_SZ * K2_P];
__device__ bf16 g_pro[(size_t)B_SZ * K4_P];
__device__ bf16 g_Wm1[(size_t)NSNP * NG_P];
__device__ bf16 g_Wm2[(size_t)K2_P * NP_P];
__device__ bf16 g_Wm3[(size_t)K3_P * NP_P];
__device__ bf16 g_Wm4[(size_t)K4_P * NP_P];
__device__ bf16 g_Wm5[(size_t)K5_P * H1_N];
__device__ bf16 g_Wm6[(size_t)H1_N * H2_N];
__device__ bf16 g_bridge[(size_t)B_SZ * K3_P];
__device__ bf16 g_fuse[(size_t)B_SZ * K5_P];
__device__ bf16 g_h1[(size_t)B_SZ * H1_N];
__device__ bf16 g_h2[(size_t)B_SZ * H2_N];
__device__ float g_b1p[NG_P];
__device__ float g_b2p[NP_P];
__device__ float g_b3p[NP_P];
__device__ float g_b4p[NP_P];

// ---------------- helpers ----------------
__device__ __forceinline__ uint32_t smem_u32(const void* p) {
    return (uint32_t)__cvta_generic_to_shared(p);
}
__device__ __forceinline__ void cp_async16(uint32_t saddr, const void* gaddr) {
    asm volatile("cp.async.cg.shared.global [%0], [%1], 16;\n" ::"r"(saddr), "l"(gaddr));
}
__device__ __forceinline__ void cp_async_commit() {
    asm volatile("cp.async.commit_group;\n" ::: "memory");
}
template <int N>
__device__ __forceinline__ void cp_async_wait() {
    asm volatile("cp.async.wait_group %0;\n" ::"n"(N) : "memory");
}

// ---------------- mask + transpose + bf16 convert ----------------
// out[kp*ldo + np] = bf16( W[n*ldw + k] * adj[k*lda + n] )   (0 outside K,N)
// grid: (Np/32, Kp/32), block (32,8)
__global__ void mask_transpose_kernel(const float* __restrict__ W, int ldw,
                                      const float* __restrict__ adj, int lda,
                                      bf16* __restrict__ out, int ldo,
                                      int K, int N) {
    __shared__ float sW[32][33];
    int k0 = blockIdx.y * 32;
    int n0 = blockIdx.x * 32;
    int tx = threadIdx.x;
    int ty = threadIdx.y;
#pragma unroll
    for (int r = 0; r < 4; r++) {
        int nl = ty + 8 * r;
        int n = n0 + nl;
        int k = k0 + tx;
        float v = 0.f;
        if (n < N && k < K) v = W[(size_t)n * ldw + k];
        sW[nl][tx] = v;
    }
    __syncthreads();
#pragma unroll
    for (int r = 0; r < 4; r++) {
        int kl = ty + 8 * r;
        int nl = tx;
        int k = k0 + kl, n = n0 + nl;
        float v = sW[nl][kl];
        if (adj != nullptr) {
            float a = (k < K && n < N) ? adj[(size_t)k * lda + n] : 0.f;
            v *= a;
        }
        out[(size_t)k * ldo + n] = __float2bfloat16(v);
    }
}

// ---------------- activation convert + zero-pad ----------------
__global__ void convert_pad_kernel(const float* __restrict__ src, int src_ld,
                                   bf16* __restrict__ dst, int dst_ld,
                                   int nvalid, int rows) {
    int idx = blockIdx.x * blockDim.x + threadIdx.x;
    int total = rows * dst_ld;
    if (idx >= total) return;
    int r = idx / dst_ld, c = idx % dst_ld;
    float v = (c < nvalid) ? src[(size_t)r * src_ld + c] : 0.f;
    dst[idx] = __float2bfloat16(v);
}

__global__ void pad_bias_kernel(const float* __restrict__ b, float* __restrict__ out,
                                int n, int np) {
    int i = blockIdx.x * blockDim.x + threadIdx.x;
    if (i < np) out[i] = (i < n) ? b[i] : 0.f;
}

// ---------------- bf16 GEMM: C[M,N] = relu(A[M,K] @ Bw[K,N] + bias) ----------------
// BM=128 BN=128 BK=32, 256 threads, 8 warps (2 m x 4 n), each warp 64x32.
// M mult of 128, N mult of 128 (via grid), K mult of 32. No bounds checks.
#define BM 128
#define BN 128
#define BKG 32

__global__ __launch_bounds__(256) void gemm_bf16_kernel(
    const bf16* __restrict__ A, int lda,
    const bf16* __restrict__ Bw, int ldb,
    bf16* __restrict__ C, int ldc,
    const float* __restrict__ bias,
    int K, int do_relu) {
    __shared__ bf16 As[2][BM][BKG + 8];
    __shared__ bf16 Bs[2][BKG][BN + 8];

    const int tid = threadIdx.x;
    const int bm = blockIdx.y * BM;
    const int bn = blockIdx.x * BN;
    const int warp = tid >> 5, lane = tid & 31;
    const int wm = (warp & 1) * 64;
    const int wn = (warp >> 1) * 32;

    float acc[4][4][4];
#pragma unroll
    for (int i = 0; i < 4; i++)
#pragma unroll
        for (int j = 0; j < 4; j++)
#pragma unroll
            for (int r = 0; r < 4; r++) acc[i][j][r] = 0.f;

    const int T = K / BKG;

    // tile loaders
    const int a_row = tid >> 2, a_seg = tid & 3;     // 64 rows/pass, 4 segs
    const int b_row = tid >> 4, b_seg = tid & 15;    // 16 rows/pass, 16 segs

    auto load_tile = [&](int t, int s) {
        int k0 = t * BKG;
#pragma unroll
        for (int p = 0; p < 2; p++) {
            int row = a_row + p * 64;
            const bf16* g = A + (size_t)(bm + row) * lda + k0 + a_seg * 8;
            cp_async16(smem_u32(&As[s][row][a_seg * 8]), g);
        }
#pragma unroll
        for (int p = 0; p < 2; p++) {
            int row = b_row + p * 16;
            const bf16* g = Bw + (size_t)(k0 + row) * ldb + bn + b_seg * 8;
            cp_async16(smem_u32(&Bs[s][row][b_seg * 8]), g);
        }
    };

    load_tile(0, 0);
    cp_async_commit();

    for (int t = 0; t < T; ++t) {
        if (t + 1 < T) load_tile(t + 1, (t + 1) & 1);
        cp_async_commit();
        cp_async_wait<1>();
        __syncthreads();

        const int s = t & 1;
#pragma unroll
        for (int kk = 0; kk < BKG; kk += 16) {
            uint32_t a[4][4];
#pragma unroll
            for (int im = 0; im < 4; im++) {
                uint32_t addr = smem_u32(&As[s][wm + im * 16 + (lane & 15)][kk + (lane >> 4) * 8]);
                asm volatile("ldmatrix.sync.aligned.m8n8.x4.shared.b16 {%0,%1,%2,%3}, [%4];"
                             : "=r"(a[im][0]), "=r"(a[im][1]), "=r"(a[im][2]), "=r"(a[im][3])
                             : "r"(addr));
            }
            uint32_t b[4][2];
#pragma unroll
            for (int ip = 0; ip < 2; ip++) {
                uint32_t r0, r1, r2, r3;
                uint32_t addr = smem_u32(&Bs[s][kk + (lane & 15)][wn + ip * 16 + (lane >> 4) * 8]);
                asm volatile("ldmatrix.sync.aligned.m8n8.x4.trans.shared.b16 {%0,%1,%2,%3}, [%4];"
                             : "=r"(r0), "=r"(r1), "=r"(r2), "=r"(r3)
                             : "r"(addr));
                b[ip * 2][0] = r0; b[ip * 2][1] = r1;
                b[ip * 2 + 1][0] = r2; b[ip * 2 + 1][1] = r3;
            }
#pragma unroll
            for (int im = 0; im < 4; im++)
#pragma unroll
                for (int jn = 0; jn < 4; jn++) {
                    asm volatile(
                        "mma.sync.aligned.m16n8k16.row.col.f32.bf16.bf16.f32 "
                        "{%0,%1,%2,%3}, {%4,%5,%6,%7}, {%8,%9}, {%0,%1,%2,%3};"
                        : "+f"(acc[im][jn][0]), "+f"(acc[im][jn][1]),
                          "+f"(acc[im][jn][2]), "+f"(acc[im][jn][3])
                        : "r"(a[im][0]), "r"(a[im][1]), "r"(a[im][2]), "r"(a[im][3]),
                          "r"(b[jn][0]), "r"(b[jn][1]));
                }
        }
        __syncthreads();
    }

    // epilogue: bias + relu + bf16 store
#pragma unroll
    for (int im = 0; im < 4; im++) {
        int r0 = bm + wm + im * 16 + (lane >> 2);
#pragma unroll
        for (int jn = 0; jn < 4; jn++) {
            int col = bn + wn + jn * 8 + (lane & 3) * 2;
            float bv0 = bias[col], bv1 = bias[col + 1];
            float f0 = acc[im][jn][0] + bv0;
            float f1 = acc[im][jn][1] + bv1;
            float f2 = acc[im][jn][2] + bv0;
            float f3 = acc[im][jn][3] + bv1;
            if (do_relu) {
                f0 = fmaxf(f0, 0.f); f1 = fmaxf(f1, 0.f);
                f2 = fmaxf(f2, 0.f); f3 = fmaxf(f3, 0.f);
            }
            *(__nv_bfloat162*)&C[(size_t)r0 * ldc + col] = __floats2bfloat162_rn(f0, f1);
            *(__nv_bfloat162*)&C[(size_t)(r0 + 8) * ldc + col] = __floats2bfloat162_rn(f2, f3);
        }
    }
}

// ---------------- final: y = sigmoid(h2 @ Wout + bout) ----------------
__global__ void final_kernel(const bf16* __restrict__ h2,
                             const float* __restrict__ Wout,
                             const float* __restrict__ bout,
                             float* __restrict__ y) {
    int row = blockIdx.x * 8 + (threadIdx.x >> 5);
    int lane = threadIdx.x & 31;
    float s = 0.f;
#pragma unroll
    for (int c = lane; c < H2_N; c += 32)
        s += __bfloat162float(h2[(size_t)row * H2_N + c]) * Wout[c];
#pragma unroll
    for (int o = 16; o; o >>= 1) s += __shfl_xor_sync(0xffffffffu, s, o);
    if (lane == 0) y[row] = 1.f / (1.f + expf(-(s + bout[0])));
}

// ---------------- launch ----------------
extern "C" void kernel_launch(void* const* d_in, const int* in_sizes, int n_in,
                              void* d_out, int out_size) {
    (void)in_sizes; (void)n_in; (void)out_size;
    const float* in_mat = (const float*)d_in[0];
    const float* adj_sg = (const float*)d_in[1];
    const float* adj_gp = (const float*)d_in[2];
    const float* adj_br = (const float*)d_in[3];
    const float* adj_pp = (const float*)d_in[4];
    const float* W_sg = (const float*)d_in[5];
    const float* b_sg = (const float*)d_in[6];
    const float* W_gp = (const float*)d_in[7];
    const float* b_gp = (const float*)d_in[8];
    const float* W_br = (const float*)d_in[9];
    const float* b_br = (const float*)d_in[10];
    const float* W_pp = (const float*)d_in[11];
    const float* b_pp = (const float*)d_in[12];
    const float* W_h1 = (const float*)d_in[13];
    const float* b_h1 = (const float*)d_in[14];
    const float* W_h2 = (const float*)d_in[15];
    const float* b_h2 = (const float*)d_in[16];
    const float* W_out = (const float*)d_in[17];
    const float* b_out = (const float*)d_in[18];
    float* y = (float*)d_out;

    bf16 *snp, *gen, *pro, *Wm1, *Wm2, *Wm3, *Wm4, *Wm5, *Wm6, *bridge, *fuse, *h1, *h2;
    float *b1p, *b2p, *b3p, *b4p;
    cudaGetSymbolAddress((void**)&snp, g_snp);
    cudaGetSymbolAddress((void**)&gen, g_gen);
    cudaGetSymbolAddress((void**)&pro, g_pro);
    cudaGetSymbolAddress((void**)&Wm1, g_Wm1);
    cudaGetSymbolAddress((void**)&Wm2, g_Wm2);
    cudaGetSymbolAddress((void**)&Wm3, g_Wm3);
    cudaGetSymbolAddress((void**)&Wm4, g_Wm4);
    cudaGetSymbolAddress((void**)&Wm5, g_Wm5);
    cudaGetSymbolAddress((void**)&Wm6, g_Wm6);
    cudaGetSymbolAddress((void**)&bridge, g_bridge);
    cudaGetSymbolAddress((void**)&fuse, g_fuse);
    cudaGetSymbolAddress((void**)&h1, g_h1);
    cudaGetSymbolAddress((void**)&h2, g_h2);
    cudaGetSymbolAddress((void**)&b1p, g_b1p);
    cudaGetSymbolAddress((void**)&b2p, g_b2p);
    cudaGetSymbolAddress((void**)&b3p, g_b3p);
    cudaGetSymbolAddress((void**)&b4p, g_b4p);

    // ---- activation converts (bf16 + zero pad) ----
    {
        int tot = B_SZ * NSNP;
        convert_pad_kernel<<<(tot + 255) / 256, 256>>>(in_mat + NPRO + NGEN, IN_COLS, snp, NSNP, NSNP, B_SZ);
    }
    {
        int tot = B_SZ * K2_P;
        convert_pad_kernel<<<(tot + 255) / 256, 256>>>(in_mat + NPRO, IN_COLS, gen, K2_P, NGEN, B_SZ);
    }
    {
        int tot = B_SZ * K4_P;
        convert_pad_kernel<<<(tot + 255) / 256, 256>>>(in_mat, IN_COLS, pro, K4_P, NPRO, B_SZ);
    }

    // ---- bias pads ----
    pad_bias_kernel<<<(NG_P + 255) / 256, 256>>>(b_sg, b1p, NGEN, NG_P);
    pad_bias_kernel<<<(NP_P + 255) / 256, 256>>>(b_gp, b2p, NPRO, NP_P);
    pad_bias_kernel<<<(NP_P + 255) / 256, 256>>>(b_br, b3p, NPRO, NP_P);
    pad_bias_kernel<<<(NP_P + 255) / 256, 256>>>(b_pp, b4p, NPRO, NP_P);

    dim3 mt(32, 8);
    // ---- masked weight preparation (transpose + mask + bf16) ----
    mask_transpose_kernel<<<dim3(NG_P / 32, NSNP / 32), mt>>>(W_sg, NSNP, adj_sg, NGEN, Wm1, NG_P, NSNP, NGEN);
    mask_transpose_kernel<<<dim3(NP_P / 32, K2_P / 32), mt>>>(W_gp, NGEN, adj_gp, NPRO, Wm2, NP_P, NGEN, NPRO);
    // bridge weight: segment A (k in [0,5120) <- W_br cols [0,5000))
    mask_transpose_kernel<<<dim3(NP_P / 32, NG_P / 32), mt>>>(W_br, NGEN + NPRO, adj_br, NPRO, Wm3, NP_P, NGEN, NPRO);
    // bridge weight: segment B (k in [5120,8192) <- W_br cols [5000,8000))
    mask_transpose_kernel<<<dim3(NP_P / 32, NP_P / 32), mt>>>(W_br + NGEN, NGEN + NPRO,
                                                             adj_br + (size_t)NGEN * NPRO, NPRO,
                                                             Wm3 + (size_t)NG_P * NP_P, NP_P, NPRO, NPRO);
    mask_transpose_kernel<<<dim3(NP_P / 32, K4_P / 32), mt>>>(W_pp, NPRO, adj_pp, NPRO, Wm4, NP_P, NPRO, NPRO);
    // h1 weight: segment A (k in [0,3072) <- W_h1 cols [0,3000))
    mask_transpose_kernel<<<dim3(H1_N / 32, NP_P / 32), mt>>>(W_h1, 2 * NPRO, nullptr, 0, Wm5, H1_N, NPRO, H1_N);
    // h1 weight: segment B (k in [3072,6144) <- W_h1 cols [3000,6000))
    mask_transpose_kernel<<<dim3(H1_N / 32, NP_P / 32), mt>>>(W_h1 + NPRO, 2 * NPRO, nullptr, 0,
                                                             Wm5 + (size_t)NP_P * H1_N, H1_N, NPRO, H1_N);
    // h2 weight
    mask_transpose_kernel<<<dim3(H2_N / 32, H1_N / 32), mt>>>(W_h2, H1_N, nullptr, 0, Wm6, H2_N, H1_N, H2_N);

    // ---- GEMMs ----
    // L1: out_snp -> bridge cols [0,5120)
    gemm_bf16_kernel<<<dim3(NG_P / BN, B_SZ / BM), 256>>>(snp, NSNP, Wm1, NG_P, bridge, K3_P, b1p, NSNP, 1);
    // L2: out_gene -> bridge cols [5120,8192)
    gemm_bf16_kernel<<<dim3(NP_P / BN, B_SZ / BM), 256>>>(gen, K2_P, Wm2, NP_P, bridge + NG_P, K3_P, b2p, K2_P, 1);
    // L3: out_bridge -> fuse cols [0,3072)
    gemm_bf16_kernel<<<dim3(NP_P / BN, B_SZ / BM), 256>>>(bridge, K3_P, Wm3, NP_P, fuse, K5_P, b3p, K3_P, 1);
    // L4: out_protein -> fuse cols [3072,6144)
    gemm_bf16_kernel<<<dim3(NP_P / BN, B_SZ / BM), 256>>>(pro, K4_P, Wm4, NP_P, fuse + NP_P, K5_P, b4p, K4_P, 1);
    // L5: h1
    gemm_bf16_kernel<<<dim3(H1_N / BN, B_SZ / BM), 256>>>(fuse, K5_P, Wm5, H1_N, h1, H1_N, b_h1, K5_P, 1);
    // L6: h2
    gemm_bf16_kernel<<<dim3(H2_N / BN, B_SZ / BM), 256>>>(h1, H1_N, Wm6, H2_N, h2, H2_N, b_h2, H1_N, 1);

    // ---- final sigmoid ----
    final_kernel<<<B_SZ / 8, 256>>>(h2, W_out, b_out, y);
}

// round 2
// speedup vs baseline: 1.1293x; 1.1293x over previous
#include <cuda_runtime.h>
#include <cuda_bf16.h>
#include <cstdint>
#include <cstdio>

typedef __nv_bfloat16 bf16;

// ---------------- problem dims ----------------
#define B_SZ   512
#define NSNP   20000
#define NGEN   5000
#define NPRO   3000
#define IN_COLS 28000     // NPRO + NGEN + NSNP
#define H1_N   1024
#define H2_N   256

// padded dims (N padded to mult of 128, K padded to mult of 32)
#define NG_P   5120
#define NP_P   3072
#define K2_P   5024
#define K3_P   8192       // bridge K = 5120 + 3072
#define K4_P   3008
#define K5_P   6144       // fuse K = 3072 + 3072

// ---------------- device scratch ----------------
__device__ bf16 g_snp[(size_t)B_SZ * NSNP];
__device__ bf16 g_gen[(size_t)B_SZ * K2_P];
__device__ bf16 g_pro[(size_t)B_SZ * K4_P];
__device__ bf16 g_Wm1[(size_t)NSNP * NG_P];
__device__ bf16 g_Wm2[(size_t)K2_P * NP_P];
__device__ bf16 g_Wm3[(size_t)K3_P * NP_P];
__device__ bf16 g_Wm4[(size_t)K4_P * NP_P];
__device__ bf16 g_Wm5[(size_t)K5_P * H1_N];
__device__ bf16 g_Wm6[(size_t)H1_N * H2_N];
__device__ bf16 g_bridge[(size_t)B_SZ * K3_P];
__device__ bf16 g_fuse[(size_t)B_SZ * K5_P];
__device__ bf16 g_h1[(size_t)B_SZ * H1_N];
__device__ bf16 g_h2[(size_t)B_SZ * H2_N];
__device__ float g_b1p[NG_P];
__device__ float g_b2p[NP_P];
__device__ float g_b3p[NP_P];
__device__ float g_b4p[NP_P];

// ---------------- helpers ----------------
__device__ __forceinline__ uint32_t smem_u32(const void* p) {
    return (uint32_t)__cvta_generic_to_shared(p);
}
__device__ __forceinline__ void cp_async16(uint32_t saddr, const void* gaddr) {
    asm volatile("cp.async.cg.shared.global [%0], [%1], 16;\n" ::"r"(saddr), "l"(gaddr));
}
__device__ __forceinline__ void cp_async_commit() {
    asm volatile("cp.async.commit_group;\n" ::: "memory");
}
template <int N>
__device__ __forceinline__ void cp_async_wait() {
    asm volatile("cp.async.wait_group %0;\n" ::"n"(N) : "memory");
}

// ---------------- mask + transpose + bf16 convert ----------------
// out[k*ldo + n] = bf16( W[n*ldw + k] * adj[k*lda + n] ), 0 outside [K,N].
// tile: 32 k-rows x 64 n-cols; block (32,8) = 256 thr.
// grid: (Np/64, Kp/32). Writes full padded tile (zeros in pad).
__global__ void mask_transpose_kernel(const float* __restrict__ W, int ldw,
                                      const float* __restrict__ adj, int lda,
                                      bf16* __restrict__ out, int ldo,
                                      int K, int N) {
    __shared__ float sW[64][33];
    const int k0 = blockIdx.y * 32;
    const int n0 = blockIdx.x * 64;
    const int lin = threadIdx.y * 32 + threadIdx.x;

    // phase 1: load W tile [64 n][32 k] via float4 (8 floats/thread)
    {
        const int rn = lin >> 2, seg = (lin & 3) * 8;
        const int gn = n0 + rn;
        const int gk = k0 + seg;
        if (gn < N && gk + 7 < K) {
            const float4 v0 = *(const float4*)&W[(size_t)gn * ldw + gk];
            const float4 v1 = *(const float4*)&W[(size_t)gn * ldw + gk + 4];
            sW[rn][seg + 0] = v0.x; sW[rn][seg + 1] = v0.y;
            sW[rn][seg + 2] = v0.z; sW[rn][seg + 3] = v0.w;
            sW[rn][seg + 4] = v1.x; sW[rn][seg + 5] = v1.y;
            sW[rn][seg + 6] = v1.z; sW[rn][seg + 7] = v1.w;
        } else {
#pragma unroll
            for (int i = 0; i < 8; i++)
                sW[rn][seg + i] = (gn < N && gk + i < K) ? W[(size_t)gn * ldw + gk + i] : 0.f;
        }
    }
    __syncthreads();

    // phase 2: each thread emits 8 n-values (16B store) for one k-row
    const int kl = lin >> 3;
    const int nb = (lin & 7) * 8;
    const int gk = k0 + kl;
    float v[8];
    if (gk < K && n0 + nb + 7 < N) {
        if (adj != nullptr) {
            const float4 a0 = *(const float4*)&adj[(size_t)gk * lda + n0 + nb];
            const float4 a1 = *(const float4*)&adj[(size_t)gk * lda + n0 + nb + 4];
            v[0] = sW[nb + 0][kl] * a0.x; v[1] = sW[nb + 1][kl] * a0.y;
            v[2] = sW[nb + 2][kl] * a0.z; v[3] = sW[nb + 3][kl] * a0.w;
            v[4] = sW[nb + 4][kl] * a1.x; v[5] = sW[nb + 5][kl] * a1.y;
            v[6] = sW[nb + 6][kl] * a1.z; v[7] = sW[nb + 7][kl] * a1.w;
        } else {
#pragma unroll
            for (int i = 0; i < 8; i++) v[i] = sW[nb + i][kl];
        }
    } else {
#pragma unroll
        for (int i = 0; i < 8; i++) {
            const int gn = n0 + nb + i;
            float x = 0.f;
            if (gk < K && gn < N) {
                x = sW[nb + i][kl];
                if (adj != nullptr) x *= adj[(size_t)gk * lda + gn];
            }
            v[i] = x;
        }
    }
    uint4 o;
    __nv_bfloat162 p;
    p = __floats2bfloat162_rn(v[0], v[1]); o.x = *(uint32_t*)&p;
    p = __floats2bfloat162_rn(v[2], v[3]); o.y = *(uint32_t*)&p;
    p = __floats2bfloat162_rn(v[4], v[5]); o.z = *(uint32_t*)&p;
    p = __floats2bfloat162_rn(v[6], v[7]); o.w = *(uint32_t*)&p;
    *(uint4*)&out[(size_t)gk * ldo + n0 + nb] = o;
}

// ---------------- activation convert + zero-pad ----------------
__global__ void convert_pad_kernel(const float* __restrict__ src, int src_ld,
                                   bf16* __restrict__ dst, int dst_ld,
                                   int nvalid, int rows) {
    int idx = blockIdx.x * blockDim.x + threadIdx.x;
    int total = rows * dst_ld;
    if (idx >= total) return;
    int r = idx / dst_ld, c = idx % dst_ld;
    float v = (c < nvalid) ? src[(size_t)r * src_ld + c] : 0.f;
    dst[idx] = __float2bfloat16(v);
}

__global__ void pad_bias_kernel(const float* __restrict__ b, float* __restrict__ out,
                                int n, int np) {
    int i = blockIdx.x * blockDim.x + threadIdx.x;
    if (i < np) out[i] = (i < n) ? b[i] : 0.f;
}

// ---------------- bf16 GEMM: C = relu(A @ Bw + bias) ----------------
// BM=128 BN=128 BK=32, 3-stage cp.async pipeline, 256 thr, 2 CTAs/SM.
#define BM 128
#define BN 128
#define BKG 32
#define AS_LD 40
#define BS_LD 136
#define STAGES 3
#define GEMM_SMEM (STAGES * (BM * AS_LD + BKG * BS_LD) * 2)

__global__ __launch_bounds__(256, 2) void gemm_bf16_kernel(
    const bf16* __restrict__ A, int lda,
    const bf16* __restrict__ Bw, int ldb,
    bf16* __restrict__ C, int ldc,
    const float* __restrict__ bias,
    int K, int do_relu) {
    extern __shared__ bf16 smem[];
    bf16* As = smem;                              // [STAGES][BM][AS_LD]
    bf16* Bs = smem + STAGES * BM * AS_LD;        // [STAGES][BKG][BS_LD]

    const int tid = threadIdx.x;
    const int bm = blockIdx.y * BM;
    const int bn = blockIdx.x * BN;
    const int warp = tid >> 5, lane = tid & 31;
    const int wm = (warp & 1) * 64;
    const int wn = (warp >> 1) * 32;

    float acc[4][4][4];
#pragma unroll
    for (int i = 0; i < 4; i++)
#pragma unroll
        for (int j = 0; j < 4; j++)
#pragma unroll
            for (int r = 0; r < 4; r++) acc[i][j][r] = 0.f;

    const int T = K / BKG;
    const int a_row = tid >> 2, a_seg = (tid & 3) * 8;
    const int b_row = tid >> 4, b_seg = (tid & 15) * 8;

#define LOAD_TILE(t, s)                                                              \
    {                                                                                \
        const int k0_ = (t) * BKG;                                                   \
        bf16* as_ = As + (s) * BM * AS_LD;                                           \
        bf16* bs_ = Bs + (s) * BKG * BS_LD;                                          \
        _Pragma("unroll") for (int p = 0; p < 2; p++) {                              \
            const int row = a_row + p * 64;                                          \
            cp_async16(smem_u32(as_ + row * AS_LD + a_seg),                          \
                       A + (size_t)(bm + row) * lda + k0_ + a_seg);                  \
        }                                                                            \
        _Pragma("unroll") for (int p = 0; p < 2; p++) {                              \
            const int row = b_row + p * 16;                                          \
            cp_async16(smem_u32(bs_ + row * BS_LD + b_seg),                          \
                       Bw + (size_t)(k0_ + row) * ldb + bn + b_seg);                 \
        }                                                                            \
    }

    LOAD_TILE(0, 0);
    cp_async_commit();
    if (T > 1) LOAD_TILE(1, 1);
    cp_async_commit();

    for (int t = 0; t < T; ++t) {
        cp_async_wait<STAGES - 2>();
        __syncthreads();

        if (t + STAGES - 1 < T) LOAD_TILE(t + STAGES - 1, (t + STAGES - 1) % STAGES);
        cp_async_commit();

        const int s = t % STAGES;
        const bf16* as_ = As + s * BM * AS_LD;
        const bf16* bs_ = Bs + s * BKG * BS_LD;
#pragma unroll
        for (int kk = 0; kk < BKG; kk += 16) {
            uint32_t a[4][4];
#pragma unroll
            for (int im = 0; im < 4; im++) {
                uint32_t addr = smem_u32(as_ + (wm + im * 16 + (lane & 15)) * AS_LD + kk + (lane >> 4) * 8);
                asm volatile("ldmatrix.sync.aligned.m8n8.x4.shared.b16 {%0,%1,%2,%3}, [%4];"
                             : "=r"(a[im][0]), "=r"(a[im][1]), "=r"(a[im][2]), "=r"(a[im][3])
                             : "r"(addr));
            }
            uint32_t b[4][2];
#pragma unroll
            for (int ip = 0; ip < 2; ip++) {
                uint32_t r0, r1, r2, r3;
                uint32_t addr = smem_u32(bs_ + (kk + (lane & 15)) * BS_LD + wn + ip * 16 + (lane >> 4) * 8);
                asm volatile("ldmatrix.sync.aligned.m8n8.x4.trans.shared.b16 {%0,%1,%2,%3}, [%4];"
                             : "=r"(r0), "=r"(r1), "=r"(r2), "=r"(r3)
                             : "r"(addr));
                b[ip * 2][0] = r0; b[ip * 2][1] = r1;
                b[ip * 2 + 1][0] = r2; b[ip * 2 + 1][1] = r3;
            }
#pragma unroll
            for (int im = 0; im < 4; im++)
#pragma unroll
                for (int jn = 0; jn < 4; jn++) {
                    asm volatile(
                        "mma.sync.aligned.m16n8k16.row.col.f32.bf16.bf16.f32 "
                        "{%0,%1,%2,%3}, {%4,%5,%6,%7}, {%8,%9}, {%0,%1,%2,%3};"
                        : "+f"(acc[im][jn][0]), "+f"(acc[im][jn][1]),
                          "+f"(acc[im][jn][2]), "+f"(acc[im][jn][3])
                        : "r"(a[im][0]), "r"(a[im][1]), "r"(a[im][2]), "r"(a[im][3]),
                          "r"(b[jn][0]), "r"(b[jn][1]));
                }
        }
        __syncthreads();
    }

#pragma unroll
    for (int im = 0; im < 4; im++) {
        int r0 = bm + wm + im * 16 + (lane >> 2);
#pragma unroll
        for (int jn = 0; jn < 4; jn++) {
            int col = bn + wn + jn * 8 + (lane & 3) * 2;
            float bv0 = bias[col], bv1 = bias[col + 1];
            float f0 = acc[im][jn][0] + bv0;
            float f1 = acc[im][jn][1] + bv1;
            float f2 = acc[im][jn][2] + bv0;
            float f3 = acc[im][jn][3] + bv1;
            if (do_relu) {
                f0 = fmaxf(f0, 0.f); f1 = fmaxf(f1, 0.f);
                f2 = fmaxf(f2, 0.f); f3 = fmaxf(f3, 0.f);
            }
            *(__nv_bfloat162*)&C[(size_t)r0 * ldc + col] = __floats2bfloat162_rn(f0, f1);
            *(__nv_bfloat162*)&C[(size_t)(r0 + 8) * ldc + col] = __floats2bfloat162_rn(f2, f3);
        }
    }
}

// ---------------- final: y = sigmoid(h2 @ Wout + bout) ----------------
__global__ void final_kernel(const bf16* __restrict__ h2,
                             const float* __restrict__ Wout,
                             const float* __restrict__ bout,
                             float* __restrict__ y) {
    int row = blockIdx.x * 8 + (threadIdx.x >> 5);
    int lane = threadIdx.x & 31;
    float s = 0.f;
#pragma unroll
    for (int c = lane; c < H2_N; c += 32)
        s += __bfloat162float(h2[(size_t)row * H2_N + c]) * Wout[c];
#pragma unroll
    for (int o = 16; o; o >>= 1) s += __shfl_xor_sync(0xffffffffu, s, o);
    if (lane == 0) y[row] = 1.f / (1.f + expf(-(s + bout[0])));
}

// ---------------- launch ----------------
extern "C" void kernel_launch(void* const* d_in, const int* in_sizes, int n_in,
                              void* d_out, int out_size) {
    (void)in_sizes; (void)n_in; (void)out_size;
    const float* in_mat = (const float*)d_in[0];
    const float* adj_sg = (const float*)d_in[1];
    const float* adj_gp = (const float*)d_in[2];
    const float* adj_br = (const float*)d_in[3];
    const float* adj_pp = (const float*)d_in[4];
    const float* W_sg = (const float*)d_in[5];
    const float* b_sg = (const float*)d_in[6];
    const float* W_gp = (const float*)d_in[7];
    const float* b_gp = (const float*)d_in[8];
    const float* W_br = (const float*)d_in[9];
    const float* b_br = (const float*)d_in[10];
    const float* W_pp = (const float*)d_in[11];
    const float* b_pp = (const float*)d_in[12];
    const float* W_h1 = (const float*)d_in[13];
    const float* b_h1 = (const float*)d_in[14];
    const float* W_h2 = (const float*)d_in[15];
    const float* b_h2 = (const float*)d_in[16];
    const float* W_out = (const float*)d_in[17];
    const float* b_out = (const float*)d_in[18];
    float* y = (float*)d_out;

    bf16 *snp, *gen, *pro, *Wm1, *Wm2, *Wm3, *Wm4, *Wm5, *Wm6, *bridge, *fuse, *h1, *h2;
    float *b1p, *b2p, *b3p, *b4p;
    cudaGetSymbolAddress((void**)&snp, g_snp);
    cudaGetSymbolAddress((void**)&gen, g_gen);
    cudaGetSymbolAddress((void**)&pro, g_pro);
    cudaGetSymbolAddress((void**)&Wm1, g_Wm1);
    cudaGetSymbolAddress((void**)&Wm2, g_Wm2);
    cudaGetSymbolAddress((void**)&Wm3, g_Wm3);
    cudaGetSymbolAddress((void**)&Wm4, g_Wm4);
    cudaGetSymbolAddress((void**)&Wm5, g_Wm5);
    cudaGetSymbolAddress((void**)&Wm6, g_Wm6);
    cudaGetSymbolAddress((void**)&bridge, g_bridge);
    cudaGetSymbolAddress((void**)&fuse, g_fuse);
    cudaGetSymbolAddress((void**)&h1, g_h1);
    cudaGetSymbolAddress((void**)&h2, g_h2);
    cudaGetSymbolAddress((void**)&b1p, g_b1p);
    cudaGetSymbolAddress((void**)&b2p, g_b2p);
    cudaGetSymbolAddress((void**)&b3p, g_b3p);
    cudaGetSymbolAddress((void**)&b4p, g_b4p);

    cudaFuncSetAttribute(gemm_bf16_kernel, cudaFuncAttributeMaxDynamicSharedMemorySize, GEMM_SMEM);

    dim3 mt(32, 8);

    // --- launches 0-4: deps of GEMM L1 + filler so launch idx 5 == GEMM L1 (ncu -s 5 -c 1) ---
    {
        int tot = B_SZ * NSNP;   // 0: snp activations
        convert_pad_kernel<<<(tot + 255) / 256, 256>>>(in_mat + NPRO + NGEN, IN_COLS, snp, NSNP, NSNP, B_SZ);
    }
    // 1: biggest masked-weight prep (W_sg)
    mask_transpose_kernel<<<dim3(NG_P / 64, NSNP / 32), mt>>>(W_sg, NSNP, adj_sg, NGEN, Wm1, NG_P, NSNP, NGEN);
    // 2-4: bias pads
    pad_bias_kernel<<<(NG_P + 255) / 256, 256>>>(b_sg, b1p, NGEN, NG_P);
    pad_bias_kernel<<<(NP_P + 255) / 256, 256>>>(b_gp, b2p, NPRO, NP_P);
    pad_bias_kernel<<<(NP_P + 255) / 256, 256>>>(b_br, b3p, NPRO, NP_P);

    // 5: GEMM L1 (profiled launch): out_snp -> bridge cols [0,5120)
    gemm_bf16_kernel<<<dim3(NG_P / BN, B_SZ / BM), 256, GEMM_SMEM>>>(snp, NSNP, Wm1, NG_P, bridge, K3_P, b1p, NSNP, 1);

    // 6: last bias pad
    pad_bias_kernel<<<(NP_P + 255) / 256, 256>>>(b_pp, b4p, NPRO, NP_P);

    // 7-8: remaining activation converts
    {
        int tot = B_SZ * K2_P;
        convert_pad_kernel<<<(tot + 255) / 256, 256>>>(in_mat + NPRO, IN_COLS, gen, K2_P, NGEN, B_SZ);
    }
    {
        int tot = B_SZ * K4_P;
        convert_pad_kernel<<<(tot + 255) / 256, 256>>>(in_mat, IN_COLS, pro, K4_P, NPRO, B_SZ);
    }

    // 9-15: remaining masked-weight preps
    mask_transpose_kernel<<<dim3(NP_P / 64, K2_P / 32), mt>>>(W_gp, NGEN, adj_gp, NPRO, Wm2, NP_P, NGEN, NPRO);
    mask_transpose_kernel<<<dim3(NP_P / 64, NG_P / 32), mt>>>(W_br, NGEN + NPRO, adj_br, NPRO, Wm3, NP_P, NGEN, NPRO);
    mask_transpose_kernel<<<dim3(NP_P / 64, NP_P / 32), mt>>>(W_br + NGEN, NGEN + NPRO,
                                                             adj_br + (size_t)NGEN * NPRO, NPRO,
                                                             Wm3 + (size_t)NG_P * NP_P, NP_P, NPRO, NPRO);
    mask_transpose_kernel<<<dim3(NP_P / 64, K4_P / 32), mt>>>(W_pp, NPRO, adj_pp, NPRO, Wm4, NP_P, NPRO, NPRO);
    mask_transpose_kernel<<<dim3(H1_N / 64, NP_P / 32), mt>>>(W_h1, 2 * NPRO, nullptr, 0, Wm5, H1_N, NPRO, H1_N);
    mask_transpose_kernel<<<dim3(H1_N / 64, NP_P / 32), mt>>>(W_h1 + NPRO, 2 * NPRO, nullptr, 0,
                                                             Wm5 + (size_t)NP_P * H1_N, H1_N, NPRO, H1_N);
    mask_transpose_kernel<<<dim3(H2_N / 64, H1_N / 32), mt>>>(W_h2, H1_N, nullptr, 0, Wm6, H2_N, H1_N, H2_N);

    // 16-20: remaining GEMMs
    gemm_bf16_kernel<<<dim3(NP_P / BN, B_SZ / BM), 256, GEMM_SMEM>>>(gen, K2_P, Wm2, NP_P, bridge + NG_P, K3_P, b2p, K2_P, 1);
    gemm_bf16_kernel<<<dim3(NP_P / BN, B_SZ / BM), 256, GEMM_SMEM>>>(pro, K4_P, Wm4, NP_P, fuse + NP_P, K5_P, b4p, K4_P, 1);
    gemm_bf16_kernel<<<dim3(NP_P / BN, B_SZ / BM), 256, GEMM_SMEM>>>(bridge, K3_P, Wm3, NP_P, fuse, K5_P, b3p, K3_P, 1);
    gemm_bf16_kernel<<<dim3(H1_N / BN, B_SZ / BM), 256, GEMM_SMEM>>>(fuse, K5_P, Wm5, H1_N, h1, H1_N, b_h1, K5_P, 1);
    gemm_bf16_kernel<<<dim3(H2_N / BN, B_SZ / BM), 256, GEMM_SMEM>>>(h1, H1_N, Wm6, H2_N, h2, H2_N, b_h2, H1_N, 1);

    // 21: final sigmoid
    final_kernel<<<B_SZ / 8, 256>>>(h2, W_out, b_out, y);
}

// round 4
// speedup vs baseline: 1.2814x; 1.1346x over previous
#include <cuda_runtime.h>
#include <cuda_bf16.h>
#include <cstdint>
#include <cstdio>

typedef __nv_bfloat16 bf16;

// ---------------- problem dims ----------------
#define B_SZ   512
#define NSNP   20000
#define NGEN   5000
#define NPRO   3000
#define IN_COLS 28000     // NPRO + NGEN + NSNP
#define H1_N   1024
#define H2_N   256

// padded dims (N padded to mult of 128, K padded to mult of 32)
#define NG_P   5120
#define NP_P   3072
#define K2_P   5024
#define K3_P   8192       // bridge K = 5120 + 3072
#define K4_P   3008
#define K5_P   6144       // fuse K = 3072 + 3072

// ---------------- device scratch ----------------
__device__ bf16 g_snp[(size_t)B_SZ * NSNP];
__device__ bf16 g_gen[(size_t)B_SZ * K2_P];
__device__ bf16 g_pro[(size_t)B_SZ * K4_P];
__device__ bf16 g_Wm1[(size_t)NSNP * NG_P];   // [k][n]
__device__ bf16 g_Wm2[(size_t)K2_P * NP_P];
__device__ bf16 g_Wm3[(size_t)K3_P * NP_P];
__device__ bf16 g_Wm4[(size_t)K4_P * NP_P];
__device__ bf16 g_Wm5[(size_t)K5_P * H1_N];
__device__ bf16 g_Wm6[(size_t)H1_N * H2_N];
__device__ bf16 g_bridge[(size_t)B_SZ * K3_P];
__device__ bf16 g_fuse[(size_t)B_SZ * K5_P];
__device__ bf16 g_h1[(size_t)B_SZ * H1_N];
__device__ bf16 g_h2[(size_t)B_SZ * H2_N];

// ---------------- helpers ----------------
__device__ __forceinline__ uint32_t smem_u32(const void* p) {
    return (uint32_t)__cvta_generic_to_shared(p);
}
__device__ __forceinline__ void cp_async16(uint32_t saddr, const void* gaddr) {
    asm volatile("cp.async.cg.shared.global [%0], [%1], 16;\n" ::"r"(saddr), "l"(gaddr));
}
__device__ __forceinline__ void cp_async_commit() {
    asm volatile("cp.async.commit_group;\n" ::: "memory");
}
template <int N>
__device__ __forceinline__ void cp_async_wait() {
    asm volatile("cp.async.wait_group %0;\n" ::"n"(N) : "memory");
}

// ---------------- mask + transpose + bf16 convert ----------------
// out[k*ldo + n] = bf16( W[n*ldw + k] * adj[k*lda + n] ), 0 outside [K,N].
// tile: 32 k x 64 n; block (32,8); grid (Np/64, Kp/32).
__global__ void mask_transpose_kernel(const float* __restrict__ W, int ldw,
                                      const float* __restrict__ adj, int lda,
                                      bf16* __restrict__ out, int ldo,
                                      int K, int N) {
    __shared__ float sW[64][33];
    const int k0 = blockIdx.y * 32;
    const int n0 = blockIdx.x * 64;
    const int lin = threadIdx.y * 32 + threadIdx.x;

    {
        const int rn = lin >> 2, seg = (lin & 3) * 8;
        const int gn = n0 + rn;
        const int gk = k0 + seg;
        if (gn < N && gk + 7 < K) {
            const float4 v0 = *(const float4*)&W[(size_t)gn * ldw + gk];
            const float4 v1 = *(const float4*)&W[(size_t)gn * ldw + gk + 4];
            sW[rn][seg + 0] = v0.x; sW[rn][seg + 1] = v0.y;
            sW[rn][seg + 2] = v0.z; sW[rn][seg + 3] = v0.w;
            sW[rn][seg + 4] = v1.x; sW[rn][seg + 5] = v1.y;
            sW[rn][seg + 6] = v1.z; sW[rn][seg + 7] = v1.w;
        } else {
#pragma unroll
            for (int i = 0; i < 8; i++)
                sW[rn][seg + i] = (gn < N && gk + i < K) ? W[(size_t)gn * ldw + gk + i] : 0.f;
        }
    }
    __syncthreads();

    const int kl = lin >> 3;
    const int nb = (lin & 7) * 8;
    const int gk = k0 + kl;
    float v[8];
    if (gk < K && n0 + nb + 7 < N) {
        if (adj != nullptr) {
            const float4 a0 = *(const float4*)&adj[(size_t)gk * lda + n0 + nb];
            const float4 a1 = *(const float4*)&adj[(size_t)gk * lda + n0 + nb + 4];
            v[0] = sW[nb + 0][kl] * a0.x; v[1] = sW[nb + 1][kl] * a0.y;
            v[2] = sW[nb + 2][kl] * a0.z; v[3] = sW[nb + 3][kl] * a0.w;
            v[4] = sW[nb + 4][kl] * a1.x; v[5] = sW[nb + 5][kl] * a1.y;
            v[6] = sW[nb + 6][kl] * a1.z; v[7] = sW[nb + 7][kl] * a1.w;
        } else {
#pragma unroll
            for (int i = 0; i < 8; i++) v[i] = sW[nb + i][kl];
        }
    } else {
#pragma unroll
        for (int i = 0; i < 8; i++) {
            const int gn = n0 + nb + i;
            float x = 0.f;
            if (gk < K && gn < N) {
                x = sW[nb + i][kl];
                if (adj != nullptr) x *= adj[(size_t)gk * lda + gn];
            }
            v[i] = x;
        }
    }
    uint4 o;
    __nv_bfloat162 p;
    p = __floats2bfloat162_rn(v[0], v[1]); o.x = *(uint32_t*)&p;
    p = __floats2bfloat162_rn(v[2], v[3]); o.y = *(uint32_t*)&p;
    p = __floats2bfloat162_rn(v[4], v[5]); o.z = *(uint32_t*)&p;
    p = __floats2bfloat162_rn(v[6], v[7]); o.w = *(uint32_t*)&p;
    *(uint4*)&out[(size_t)gk * ldo + n0 + nb] = o;
}

// ---------------- activation convert + zero-pad ----------------
__global__ void convert_pad_kernel(const float* __restrict__ src, int src_ld,
                                   bf16* __restrict__ dst, int dst_ld,
                                   int nvalid, int rows) {
    int idx = blockIdx.x * blockDim.x + threadIdx.x;
    int total = rows * dst_ld;
    if (idx >= total) return;
    int r = idx / dst_ld, c = idx % dst_ld;
    float v = (c < nvalid) ? src[(size_t)r * src_ld + c] : 0.f;
    dst[idx] = __float2bfloat16(v);
}

// ---------------- bf16 GEMM: C = relu(A @ Bw + bias) ----------------
// BM=128 BN=128 BK=32, 4 warps (2x2), warp tile 64x64, 3-stage cp.async,
// 128 threads, 2 CTAs/SM.
#define BM 128
#define BN 128
#define BKG 32
#define AS_LD 40
#define BS_LD 136
#define STAGES 3
#define GEMM_SMEM (STAGES * (BM * AS_LD + BKG * BS_LD) * 2)

__global__ __launch_bounds__(128, 2) void gemm_bf16_kernel(
    const bf16* __restrict__ A, int lda,
    const bf16* __restrict__ Bw, int ldb,
    bf16* __restrict__ C, int ldc,
    const float* __restrict__ bias, int Nreal,
    int K, int do_relu) {
    extern __shared__ bf16 smem[];
    bf16* As = smem;                              // [STAGES][BM][AS_LD]
    bf16* Bs = smem + STAGES * BM * AS_LD;        // [STAGES][BKG][BS_LD]

    const int tid = threadIdx.x;
    const int bm = blockIdx.y * BM;
    const int bn = blockIdx.x * BN;
    const int warp = tid >> 5, lane = tid & 31;
    const int wm = (warp & 1) * 64;
    const int wn = (warp >> 1) * 64;

    float acc[4][8][4];
#pragma unroll
    for (int i = 0; i < 4; i++)
#pragma unroll
        for (int j = 0; j < 8; j++)
#pragma unroll
            for (int r = 0; r < 4; r++) acc[i][j][r] = 0.f;

    const int T = K / BKG;
    // A tile: 128 rows x 32 cols = 128x4 segs of 8 bf16; 128 thr -> 4 each
    const int a_row = tid >> 2, a_seg = (tid & 3) * 8;
    // B tile: 32 rows x 128 cols = 32x16 segs; 128 thr -> 4 each
    const int b_row = tid >> 4, b_seg = (tid & 15) * 8;

#define LOAD_TILE(t, s)                                                              \
    {                                                                                \
        const int k0_ = (t) * BKG;                                                   \
        bf16* as_ = As + (s) * BM * AS_LD;                                           \
        bf16* bs_ = Bs + (s) * BKG * BS_LD;                                          \
        _Pragma("unroll") for (int p = 0; p < 4; p++) {                              \
            const int row = a_row + p * 32;                                          \
            cp_async16(smem_u32(as_ + row * AS_LD + a_seg),                          \
                       A + (size_t)(bm + row) * lda + k0_ + a_seg);                  \
        }                                                                            \
        _Pragma("unroll") for (int p = 0; p < 4; p++) {                              \
            const int row = b_row + p * 8;                                           \
            cp_async16(smem_u32(bs_ + row * BS_LD + b_seg),                          \
                       Bw + (size_t)(k0_ + row) * ldb + bn + b_seg);                 \
        }                                                                            \
    }

    LOAD_TILE(0, 0);
    cp_async_commit();
    if (T > 1) LOAD_TILE(1, 1);
    cp_async_commit();

    for (int t = 0; t < T; ++t) {
        cp_async_wait<STAGES - 2>();
        __syncthreads();

        if (t + STAGES - 1 < T) LOAD_TILE(t + STAGES - 1, (t + STAGES - 1) % STAGES);
        cp_async_commit();

        const int s = t % STAGES;
        const bf16* as_ = As + s * BM * AS_LD;
        const bf16* bs_ = Bs + s * BKG * BS_LD;
#pragma unroll
        for (int kk = 0; kk < BKG; kk += 16) {
            uint32_t a[4][4];
#pragma unroll
            for (int im = 0; im < 4; im++) {
                uint32_t addr = smem_u32(as_ + (wm + im * 16 + (lane & 15)) * AS_LD + kk + (lane >> 4) * 8);
                asm volatile("ldmatrix.sync.aligned.m8n8.x4.shared.b16 {%0,%1,%2,%3}, [%4];"
                             : "=r"(a[im][0]), "=r"(a[im][1]), "=r"(a[im][2]), "=r"(a[im][3])
                             : "r"(addr));
            }
            uint32_t b[8][2];
#pragma unroll
            for (int ip = 0; ip < 4; ip++) {
                uint32_t r0, r1, r2, r3;
                uint32_t addr = smem_u32(bs_ + (kk + (lane & 15)) * BS_LD + wn + ip * 16 + (lane >> 4) * 8);
                asm volatile("ldmatrix.sync.aligned.m8n8.x4.trans.shared.b16 {%0,%1,%2,%3}, [%4];"
                             : "=r"(r0), "=r"(r1), "=r"(r2), "=r"(r3)
                             : "r"(addr));
                b[ip * 2][0] = r0; b[ip * 2][1] = r1;
                b[ip * 2 + 1][0] = r2; b[ip * 2 + 1][1] = r3;
            }
#pragma unroll
            for (int im = 0; im < 4; im++)
#pragma unroll
                for (int jn = 0; jn < 8; jn++) {
                    asm volatile(
                        "mma.sync.aligned.m16n8k16.row.col.f32.bf16.bf16.f32 "
                        "{%0,%1,%2,%3}, {%4,%5,%6,%7}, {%8,%9}, {%0,%1,%2,%3};"
                        : "+f"(acc[im][jn][0]), "+f"(acc[im][jn][1]),
                          "+f"(acc[im][jn][2]), "+f"(acc[im][jn][3])
                        : "r"(a[im][0]), "r"(a[im][1]), "r"(a[im][2]), "r"(a[im][3]),
                          "r"(b[jn][0]), "r"(b[jn][1]));
                }
        }
        __syncthreads();
    }

    // epilogue: bias (guarded) + relu + bf16 store
#pragma unroll
    for (int im = 0; im < 4; im++) {
        int r0 = bm + wm + im * 16 + (lane >> 2);
#pragma unroll
        for (int jn = 0; jn < 8; jn++) {
            int col = bn + wn + jn * 8 + (lane & 3) * 2;
            float bv0 = (col < Nreal) ? bias[col] : 0.f;
            float bv1 = (col + 1 < Nreal) ? bias[col + 1] : 0.f;
            float f0 = acc[im][jn][0] + bv0;
            float f1 = acc[im][jn][1] + bv1;
            float f2 = acc[im][jn][2] + bv0;
            float f3 = acc[im][jn][3] + bv1;
            if (do_relu) {
                f0 = fmaxf(f0, 0.f); f1 = fmaxf(f1, 0.f);
                f2 = fmaxf(f2, 0.f); f3 = fmaxf(f3, 0.f);
            }
            *(__nv_bfloat162*)&C[(size_t)r0 * ldc + col] = __floats2bfloat162_rn(f0, f1);
            *(__nv_bfloat162*)&C[(size_t)(r0 + 8) * ldc + col] = __floats2bfloat162_rn(f2, f3);
        }
    }
}

// ---------------- final: y = sigmoid(h2 @ Wout + bout) ----------------
__global__ void final_kernel(const bf16* __restrict__ h2,
                             const float* __restrict__ Wout,
                             const float* __restrict__ bout,
                             float* __restrict__ y) {
    int row = blockIdx.x * 8 + (threadIdx.x >> 5);
    int lane = threadIdx.x & 31;
    float s = 0.f;
#pragma unroll
    for (int c = lane; c < H2_N; c += 32)
        s += __bfloat162float(h2[(size_t)row * H2_N + c]) * Wout[c];
#pragma unroll
    for (int o = 16; o; o >>= 1) s += __shfl_xor_sync(0xffffffffu, s, o);
    if (lane == 0) y[row] = 1.f / (1.f + expf(-(s + bout[0])));
}

// ---------------- launch ----------------
extern "C" void kernel_launch(void* const* d_in, const int* in_sizes, int n_in,
                              void* d_out, int out_size) {
    (void)in_sizes; (void)n_in; (void)out_size;
    const float* in_mat = (const float*)d_in[0];
    const float* adj_sg = (const float*)d_in[1];
    const float* adj_gp = (const float*)d_in[2];
    const float* adj_br = (const float*)d_in[3];
    const float* adj_pp = (const float*)d_in[4];
    const float* W_sg = (const float*)d_in[5];
    const float* b_sg = (const float*)d_in[6];
    const float* W_gp = (const float*)d_in[7];
    const float* b_gp = (const float*)d_in[8];
    const float* W_br = (const float*)d_in[9];
    const float* b_br = (const float*)d_in[10];
    const float* W_pp = (const float*)d_in[11];
    const float* b_pp = (const float*)d_in[12];
    const float* W_h1 = (const float*)d_in[13];
    const float* b_h1 = (const float*)d_in[14];
    const float* W_h2 = (const float*)d_in[15];
    const float* b_h2 = (const float*)d_in[16];
    const float* W_out = (const float*)d_in[17];
    const float* b_out = (const float*)d_in[18];
    float* y = (float*)d_out;

    bf16 *snp, *gen, *pro, *Wm1, *Wm2, *Wm3, *Wm4, *Wm5, *Wm6, *bridge, *fuse, *h1, *h2;
    cudaGetSymbolAddress((void**)&snp, g_snp);
    cudaGetSymbolAddress((void**)&gen, g_gen);
    cudaGetSymbolAddress((void**)&pro, g_pro);
    cudaGetSymbolAddress((void**)&Wm1, g_Wm1);
    cudaGetSymbolAddress((void**)&Wm2, g_Wm2);
    cudaGetSymbolAddress((void**)&Wm3, g_Wm3);
    cudaGetSymbolAddress((void**)&Wm4, g_Wm4);
    cudaGetSymbolAddress((void**)&Wm5, g_Wm5);
    cudaGetSymbolAddress((void**)&Wm6, g_Wm6);
    cudaGetSymbolAddress((void**)&bridge, g_bridge);
    cudaGetSymbolAddress((void**)&fuse, g_fuse);
    cudaGetSymbolAddress((void**)&h1, g_h1);
    cudaGetSymbolAddress((void**)&h2, g_h2);

    cudaFuncSetAttribute(gemm_bf16_kernel, cudaFuncAttributeMaxDynamicSharedMemorySize, GEMM_SMEM);

    dim3 mt(32, 8);

    // ---- activation converts ----
    {
        int tot = B_SZ * NSNP;
        convert_pad_kernel<<<(tot + 255) / 256, 256>>>(in_mat + NPRO + NGEN, IN_COLS, snp, NSNP, NSNP, B_SZ);
    }
    {
        int tot = B_SZ * K2_P;
        convert_pad_kernel<<<(tot + 255) / 256, 256>>>(in_mat + NPRO, IN_COLS, gen, K2_P, NGEN, B_SZ);
    }
    {
        int tot = B_SZ * K4_P;
        convert_pad_kernel<<<(tot + 255) / 256, 256>>>(in_mat, IN_COLS, pro, K4_P, NPRO, B_SZ);
    }

    // ---- masked weight prep ([k][n] bf16, zero-padded) ----
    mask_transpose_kernel<<<dim3(NG_P / 64, NSNP / 32), mt>>>(W_sg, NSNP, adj_sg, NGEN, Wm1, NG_P, NSNP, NGEN);
    mask_transpose_kernel<<<dim3(NP_P / 64, K2_P / 32), mt>>>(W_gp, NGEN, adj_gp, NPRO, Wm2, NP_P, NGEN, NPRO);
    mask_transpose_kernel<<<dim3(NP_P / 64, NG_P / 32), mt>>>(W_br, NGEN + NPRO, adj_br, NPRO, Wm3, NP_P, NGEN, NPRO);
    mask_transpose_kernel<<<dim3(NP_P / 64, NP_P / 32), mt>>>(W_br + NGEN, NGEN + NPRO,
                                                             adj_br + (size_t)NGEN * NPRO, NPRO,
                                                             Wm3 + (size_t)NG_P * NP_P, NP_P, NPRO, NPRO);
    mask_transpose_kernel<<<dim3(NP_P / 64, K4_P / 32), mt>>>(W_pp, NPRO, adj_pp, NPRO, Wm4, K4_P == K4_P ? NP_P : NP_P, NPRO, NPRO);
    mask_transpose_kernel<<<dim3(H1_N / 64, NP_P / 32), mt>>>(W_h1, 2 * NPRO, nullptr, 0, Wm5, H1_N, NPRO, H1_N);
    mask_transpose_kernel<<<dim3(H1_N / 64, NP_P / 32), mt>>>(W_h1 + NPRO, 2 * NPRO, nullptr, 0,
                                                             Wm5 + (size_t)NP_P * H1_N, H1_N, NPRO, H1_N);
    mask_transpose_kernel<<<dim3(H2_N / 64, H1_N / 32), mt>>>(W_h2, H1_N, nullptr, 0, Wm6, H2_N, H1_N, H2_N);

    // ---- GEMMs ----
    gemm_bf16_kernel<<<dim3(NG_P / BN, B_SZ / BM), 128, GEMM_SMEM>>>(snp, NSNP, Wm1, NG_P, bridge, K3_P, b_sg, NGEN, NSNP, 1);
    gemm_bf16_kernel<<<dim3(NP_P / BN, B_SZ / BM), 128, GEMM_SMEM>>>(gen, K2_P, Wm2, NP_P, bridge + NG_P, K3_P, b_gp, NPRO, K2_P, 1);
    gemm_bf16_kernel<<<dim3(NP_P / BN, B_SZ / BM), 128, GEMM_SMEM>>>(pro, K4_P, Wm4, NP_P, fuse + NP_P, K5_P, b_pp, NPRO, K4_P, 1);
    gemm_bf16_kernel<<<dim3(NP_P / BN, B_SZ / BM), 128, GEMM_SMEM>>>(bridge, K3_P, Wm3, NP_P, fuse, K5_P, b_br, NPRO, K3_P, 1);
    gemm_bf16_kernel<<<dim3(H1_N / BN, B_SZ / BM), 128, GEMM_SMEM>>>(fuse, K5_P, Wm5, H1_N, h1, H1_N, b_h1, H1_N, K5_P, 1);
    gemm_bf16_kernel<<<dim3(H2_N / BN, B_SZ / BM), 128, GEMM_SMEM>>>(h1, H1_N, Wm6, H2_N, h2, H2_N, b_h2, H2_N, H1_N, 1);

    // ---- final sigmoid ----
    final_kernel<<<B_SZ / 8, 256>>>(h2, W_out, b_out, y);
}